// round 11
// baseline (speedup 1.0000x reference)
#include <cuda_runtime.h>
#include <cstdint>

#define BB 8
#define NN 256
#define FF 64
#define ROWS (BB * NN)                 // 2048
#define W_ELEMS ((size_t)BB * NN * NN * FF)  // 33,554,432

#define TILE_J 32
#define TILE_BYTES (TILE_J * FF * 4)   // 8192
#define NSTAGES 3
#define RPB 2                          // rows per block
#define NBLK (ROWS / RPB)              // 1024
#define NT_TOT (RPB * (NN / TILE_J))   // 16 tiles per block
#define MLP_NB 256                     // blocks that run the MLP (8 x-rows each)

// Scratch (allocation-free rule: __device__ globals).
__device__ __align__(16) float g_x1[ROWS * FF];  // relu MLP(n) of x
__device__ __align__(16) float g_s[ROWS * FF];   // relu MLP(s) of x
__device__ int g_cnt[BB];       // per-batch mlp completion counters (target 32)
__device__ unsigned g_fin = 0;  // finish counter for replay-deterministic reset

// ---------------------------------------------------------------------------
// PTX helpers
// ---------------------------------------------------------------------------
__device__ __forceinline__ uint32_t s2u(const void* p) {
    return (uint32_t)__cvta_generic_to_shared(p);
}
__device__ __forceinline__ void mbar_init(uint32_t mbar, uint32_t count) {
    asm volatile("mbarrier.init.shared.b64 [%0], %1;" :: "r"(mbar), "r"(count) : "memory");
}
__device__ __forceinline__ void mbar_expect_tx(uint32_t mbar, uint32_t bytes) {
    asm volatile("mbarrier.arrive.expect_tx.shared.b64 _, [%0], %1;"
                 :: "r"(mbar), "r"(bytes) : "memory");
}
__device__ __forceinline__ void mbar_wait(uint32_t mbar, uint32_t parity) {
    uint32_t done;
    asm volatile(
        "{\n\t.reg .pred p;\n\t"
        "mbarrier.try_wait.parity.acquire.cta.shared::cta.b64 p, [%1], %2;\n\t"
        "selp.b32 %0, 1, 0, p;\n\t}"
        : "=r"(done) : "r"(mbar), "r"(parity) : "memory");
    while (!done) {
        asm volatile(
            "{\n\t.reg .pred p;\n\t"
            "mbarrier.try_wait.parity.acquire.cta.shared::cta.b64 p, [%1], %2, 0x989680;\n\t"
            "selp.b32 %0, 1, 0, p;\n\t}"
            : "=r"(done) : "r"(mbar), "r"(parity) : "memory");
    }
}
__device__ __forceinline__ void bulk_g2s(uint32_t dst_smem, const void* src,
                                         uint32_t bytes, uint32_t mbar) {
    asm volatile(
        "cp.async.bulk.shared::cluster.global.mbarrier::complete_tx::bytes "
        "[%0], [%1], %2, [%3];"
        :: "r"(dst_smem), "l"(src), "r"(bytes), "r"(mbar) : "memory");
}
__device__ __forceinline__ void bulk_s2g(void* dst, uint32_t src_smem, uint32_t bytes) {
    asm volatile("cp.async.bulk.global.shared::cta.bulk_group [%0], [%1], %2;"
                 :: "l"(dst), "r"(src_smem), "r"(bytes) : "memory");
}
__device__ __forceinline__ void bulk_commit() {
    asm volatile("cp.async.bulk.commit_group;" ::: "memory");
}
// FULL completion wait — the proven-correct gating (.read caused corruption).
__device__ __forceinline__ void bulk_wait_all() {
    asm volatile("cp.async.bulk.wait_group 0;" ::: "memory");
}
__device__ __forceinline__ void fence_proxy_async_cta() {
    asm volatile("fence.proxy.async.shared::cta;" ::: "memory");
}

// ---------------------------------------------------------------------------
// ONE fused kernel. Grid = 1024 blocks, each owning rows 2*bi, 2*bi+1
// (7 blocks/SM -> the entire grid is resident in one wave; each block
// streams a contiguous 128KB W span).
//   Blocks 0..255: first run both MLPs for x-rows [8*bi, 8*bi+8) with
//   weights STAGED IN THE TILE SMEM (fast, ~2us), then bump the per-batch
//   counter and join the streaming path.
//   Blocks 256..1023: issue A-row loads + 2 TMA W-tile prefetches
//   immediately (their DRAM traffic covers the MLP phase), then spin on
//   their batch's counter.
// Main loop = R7-proven 3-stage ring: prefetch depth 2, TMA bulk stores,
// full wait_group 0 before stage overwrite. x2 epilogue at tiles 7 and 15.
// ---------------------------------------------------------------------------
__global__ __launch_bounds__(256, 7) void fused_kernel(
    const float* __restrict__ A,
    const char* __restrict__ W,
    const float* __restrict__ x,
    const float* __restrict__ nw1, const float* __restrict__ nb1,
    const float* __restrict__ nw2, const float* __restrict__ nb2,
    const float* __restrict__ sw1, const float* __restrict__ sb1,
    const float* __restrict__ sw2, const float* __restrict__ sb2,
    char* __restrict__ outW,
    float* __restrict__ outX2)
{
    __shared__ __align__(128) char tile[NSTAGES][TILE_BYTES];   // 24KB
    __shared__ __align__(8) unsigned long long mbar_st[NSTAGES];
    __shared__ float sAn[RPB][NN];          // 2KB
    __shared__ float4 red2[8][16];          // 0.5KB
    __shared__ float warp_s[RPB][8];
    __shared__ float sden[RPB];
    __shared__ __align__(8) float2 sxP[FF][4];   // mlp: x pairs, 2KB
    __shared__ __align__(8) float2 shP[FF][4];   // mlp: hidden pairs, 2KB

    int bi  = blockIdx.x;
    int tid = threadIdx.x;
    int r0  = bi * RPB;            // first owned row
    int b   = r0 >> 8;             // batch of both owned rows

    uint32_t mb[NSTAGES] = { s2u(&mbar_st[0]), s2u(&mbar_st[1]), s2u(&mbar_st[2]) };
    uint32_t tu[NSTAGES] = { s2u(&tile[0][0]), s2u(&tile[1][0]), s2u(&tile[2][0]) };
    if (tid < NSTAGES) mbar_init(mb[tid], 1);

    bool is_mlp = (bi < MLP_NB);

    if (is_mlp) {
        // ---- MLP phase for x-rows [8*bi, 8*bi+8) ----
        int R0 = bi * 8;
        int e = tid & 63;
        int g = tid >> 6;            // row-pair 0..3 (rows 2g, 2g+1 local)

        // Load x transposed into pair layout (128 threads, coalesced).
        if (tid < 128) {
            float4 v = ((const float4*)(x + (size_t)R0 * FF))[tid];
            int row = tid >> 4;          // local row 0..7
            int k0  = (tid & 15) * 4;
            ((float*)&sxP[k0 + 0][row >> 1])[row & 1] = v.x;
            ((float*)&sxP[k0 + 1][row >> 1])[row & 1] = v.y;
            ((float*)&sxP[k0 + 2][row >> 1])[row & 1] = v.z;
            ((float*)&sxP[k0 + 3][row >> 1])[row & 1] = v.w;
        }

        const float* tileF = (const float*)tile[0];   // staged weight view

        for (int p = 0; p < 2; p++) {   // p=0: n-MLP -> g_x1 ; p=1: s-MLP -> g_s
            const float* w1 = p ? sw1 : nw1;
            const float* w2 = p ? sw2 : nw2;
            const float* b1 = p ? sb1 : nb1;
            const float* b2 = p ? sb2 : nb2;

            // Stage layer-1 weights (16KB) into tile[0..1].
            #pragma unroll
            for (int jj = 0; jj < 4; jj++)
                ((float4*)tile[0])[tid + jj * 256] = ((const float4*)w1)[tid + jj * 256];
            __syncthreads();    // staging + x-transpose (p=0) visible

            float bias = __ldg(&b1[e]);
            float h0 = bias, h1 = bias;
            #pragma unroll
            for (int k = 0; k < FF; k++) {
                float  w  = tileF[k * FF + e];
                float2 xv = sxP[k][g];
                h0 = fmaf(w, xv.x, h0);
                h1 = fmaf(w, xv.y, h1);
            }
            __syncthreads();    // w1 reads done before restage; prev shP consumed
            shP[e][g] = make_float2(fmaxf(h0, 0.f), fmaxf(h1, 0.f));

            // Stage layer-2 weights.
            #pragma unroll
            for (int jj = 0; jj < 4; jj++)
                ((float4*)tile[0])[tid + jj * 256] = ((const float4*)w2)[tid + jj * 256];
            __syncthreads();

            float bias2 = __ldg(&b2[e]);
            float c0 = bias2, c1 = bias2;
            #pragma unroll
            for (int k = 0; k < FF; k++) {
                float  w  = tileF[k * FF + e];
                float2 hv = shP[k][g];
                c0 = fmaf(w, hv.x, c0);
                c1 = fmaf(w, hv.y, c1);
            }
            float* out = p ? g_s : g_x1;
            out[(size_t)(R0 + 2 * g + 0) * FF + e] = fmaxf(c0, 0.f);
            out[(size_t)(R0 + 2 * g + 1) * FF + e] = fmaxf(c1, 0.f);
            __syncthreads();    // w2 reads done before next restage / TMA
        }

        __threadfence();        // release g_x1/g_s globally
        __syncthreads();        // all threads' fences before the signal
        if (tid == 0) atomicAdd(&g_cnt[bi >> 5], 1);
    }

    // ---- A rows: L1 denominators for both owned rows ----
    float a0 = A[(size_t)r0 * NN + tid];
    float a1 = A[(size_t)(r0 + 1) * NN + tid];
    float v0 = fabsf(a0), v1 = fabsf(a1);
    #pragma unroll
    for (int off = 16; off; off >>= 1) {
        v0 += __shfl_xor_sync(0xffffffffu, v0, off);
        v1 += __shfl_xor_sync(0xffffffffu, v1, off);
    }
    if ((tid & 31) == 0) {
        warp_s[0][tid >> 5] = v0;
        warp_s[1][tid >> 5] = v1;
    }
    __syncthreads();            // warp_s ready; mbar init visible

    const char* Wbase = W    + (size_t)r0 * (NN * FF * 4);   // 128KB contiguous
    char*       Obase = outW + (size_t)r0 * (NN * FF * 4);

    if (tid < RPB) {
        float t = 0.f;
        #pragma unroll
        for (int w = 0; w < 8; w++) t += warp_s[tid][w];
        sden[tid] = fmaxf(t, 1e-12f);
    }
    if (tid == 0) {
        if (is_mlp) fence_proxy_async_cta();   // generic tile use -> async proxy
        // Prefetch tiles 0,1 (streams during the MLP phase for non-mlp blocks).
        mbar_expect_tx(mb[0], TILE_BYTES);
        bulk_g2s(tu[0], Wbase, TILE_BYTES, mb[0]);
        mbar_expect_tx(mb[1], TILE_BYTES);
        bulk_g2s(tu[1], Wbase + TILE_BYTES, TILE_BYTES, mb[1]);
    }
    __syncthreads();
    sAn[0][tid] = a0 / sden[0];
    sAn[1][tid] = a1 / sden[1];

    // ---- wait for this batch's MLP outputs (per-batch release) ----
    if (tid == 0) {
        while (*((volatile int*)&g_cnt[b]) < 32) __nanosleep(64);
        __threadfence();       // acquire
    }
    __syncthreads();           // sAn ready + mlp outputs visible to all threads

    const float4* x1b = ((const float4*)g_x1) + (size_t)b * (NN * 16);
    int e4 = tid & 15;    // float4 lane (features e4*4 .. e4*4+3)
    int jg = tid >> 4;    // j group 0..15 within tile

    float4 acc = make_float4(0.f, 0.f, 0.f, 0.f);

    for (int t = 0; t < NT_TOT; t++) {
        int s  = t % NSTAGES;
        int ph = (t / NSTAGES) & 1;
        mbar_wait(mb[s], ph);   // tile t resident in stage s

        if (tid == 0) {
            if (t + 2 < NT_TOT) {
                // Dest stage held tile t-1: consumers passed iter t-1's end
                // barrier; its copy-out store must be fully drained.
                bulk_wait_all();
                int sd = (t + 2) % NSTAGES;
                mbar_expect_tx(mb[sd], TILE_BYTES);
                bulk_g2s(tu[sd], Wbase + (size_t)(t + 2) * TILE_BYTES,
                         TILE_BYTES, mb[sd]);
            }
            bulk_s2g(Obase + (size_t)t * TILE_BYTES, tu[s], TILE_BYTES);
            bulk_commit();
        }

        int r  = t >> 3;              // owned-row index 0/1
        int tj = (t & 7) * TILE_J;    // j offset of this tile within the row
        const float4* Wt = (const float4*)tile[s];
        #pragma unroll
        for (int k = 0; k < TILE_J / 16; k++) {
            int jl = jg + 16 * k;
            int j  = tj + jl;
            float4 w   = Wt[jl * 16 + e4];
            float4 x1v = x1b[j * 16 + e4];
            float  tt  = sAn[r][j];
            acc.x = fmaf(tt * w.x, x1v.x, acc.x);
            acc.y = fmaf(tt * w.y, x1v.y, acc.y);
            acc.z = fmaf(tt * w.z, x1v.z, acc.z);
            acc.w = fmaf(tt * w.w, x1v.w, acc.w);
        }

        if ((t & 7) == 7) {
            // x2 epilogue for row r0 + r.
            acc.x += __shfl_xor_sync(0xffffffffu, acc.x, 16);
            acc.y += __shfl_xor_sync(0xffffffffu, acc.y, 16);
            acc.z += __shfl_xor_sync(0xffffffffu, acc.z, 16);
            acc.w += __shfl_xor_sync(0xffffffffu, acc.w, 16);
            if ((tid & 31) < 16) red2[tid >> 5][e4] = acc;
            __syncthreads();
            if (tid < 16) {
                float4 rr = red2[0][tid];
                #pragma unroll
                for (int w = 1; w < 8; w++) {
                    float4 tv = red2[w][tid];
                    rr.x += tv.x; rr.y += tv.y; rr.z += tv.z; rr.w += tv.w;
                }
                float4 sv = ((const float4*)g_s)[(size_t)(r0 + r) * 16 + tid];
                rr.x += sv.x; rr.y += sv.y; rr.z += sv.z; rr.w += sv.w;
                ((float4*)outX2)[(size_t)(r0 + r) * 16 + tid] = rr;
            }
            acc = make_float4(0.f, 0.f, 0.f, 0.f);
        }
        __syncthreads();   // all consumers done with stage s before reload
    }

    if (tid == 0) {
        bulk_wait_all();   // drain W-tile stores
        // Replay-determinism: last finishing block resets sync state.
        unsigned f = atomicAdd(&g_fin, 1u);
        if (f == (unsigned)(NBLK - 1)) {
            #pragma unroll
            for (int i = 0; i < BB; i++) g_cnt[i] = 0;
            g_fin = 0u;
            __threadfence();
        }
    }
}

// ---------------------------------------------------------------------------
extern "C" void kernel_launch(void* const* d_in, const int* in_sizes, int n_in,
                              void* d_out, int out_size)
{
    const float* A   = (const float*)d_in[0];
    const float* W   = (const float*)d_in[1];
    const float* x   = (const float*)d_in[2];
    const float* nw1 = (const float*)d_in[3];
    const float* nb1 = (const float*)d_in[4];
    const float* nw2 = (const float*)d_in[5];
    const float* nb2 = (const float*)d_in[6];
    const float* sw1 = (const float*)d_in[7];
    const float* sb1 = (const float*)d_in[8];
    const float* sw2 = (const float*)d_in[9];
    const float* sb2 = (const float*)d_in[10];

    float* outW  = (float*)d_out;            // W passthrough, 33,554,432 floats
    float* outX2 = (float*)d_out + W_ELEMS;  // x2, 131,072 floats

    fused_kernel<<<NBLK, 256>>>(A, (const char*)W, x,
                                nw1, nb1, nw2, nb2,
                                sw1, sb1, sw2, sb2,
                                (char*)outW, outX2);
}

// round 12
// speedup vs baseline: 1.1886x; 1.1886x over previous
#include <cuda_runtime.h>
#include <cstdint>

#define BB 8
#define NN 256
#define FF 64
#define ROWS (BB * NN)          // 2048
#define W_ELEMS ((size_t)BB * NN * NN * FF)  // 33,554,432

#define TILE_J 32
#define TILE_BYTES (TILE_J * FF * 4)   // 8192
#define NTILES (NN / TILE_J)           // 8
#define NSTAGES 3

// Scratch (allocation-free rule: __device__ globals), 16B aligned for float4.
__device__ __align__(16) float g_x1[ROWS * FF];  // relu MLP(n) of x
__device__ __align__(16) float g_s[ROWS * FF];   // relu MLP(s) of x

// ---------------------------------------------------------------------------
// PTX helpers
// ---------------------------------------------------------------------------
__device__ __forceinline__ uint32_t s2u(const void* p) {
    return (uint32_t)__cvta_generic_to_shared(p);
}
__device__ __forceinline__ void mbar_init(uint32_t mbar, uint32_t count) {
    asm volatile("mbarrier.init.shared.b64 [%0], %1;" :: "r"(mbar), "r"(count) : "memory");
}
__device__ __forceinline__ void mbar_expect_tx(uint32_t mbar, uint32_t bytes) {
    asm volatile("mbarrier.arrive.expect_tx.shared.b64 _, [%0], %1;"
                 :: "r"(mbar), "r"(bytes) : "memory");
}
__device__ __forceinline__ void mbar_wait(uint32_t mbar, uint32_t parity) {
    uint32_t done;
    asm volatile(
        "{\n\t.reg .pred p;\n\t"
        "mbarrier.try_wait.parity.acquire.cta.shared::cta.b64 p, [%1], %2;\n\t"
        "selp.b32 %0, 1, 0, p;\n\t}"
        : "=r"(done) : "r"(mbar), "r"(parity) : "memory");
    while (!done) {
        asm volatile(
            "{\n\t.reg .pred p;\n\t"
            "mbarrier.try_wait.parity.acquire.cta.shared::cta.b64 p, [%1], %2, 0x989680;\n\t"
            "selp.b32 %0, 1, 0, p;\n\t}"
            : "=r"(done) : "r"(mbar), "r"(parity) : "memory");
    }
}
__device__ __forceinline__ void bulk_g2s(uint32_t dst_smem, const void* src,
                                         uint32_t bytes, uint32_t mbar) {
    asm volatile(
        "cp.async.bulk.shared::cluster.global.mbarrier::complete_tx::bytes "
        "[%0], [%1], %2, [%3];"
        :: "r"(dst_smem), "l"(src), "r"(bytes), "r"(mbar) : "memory");
}
__device__ __forceinline__ void bulk_s2g(void* dst, uint32_t src_smem, uint32_t bytes) {
    asm volatile("cp.async.bulk.global.shared::cta.bulk_group [%0], [%1], %2;"
                 :: "l"(dst), "r"(src_smem), "r"(bytes) : "memory");
}
__device__ __forceinline__ void bulk_commit() {
    asm volatile("cp.async.bulk.commit_group;" ::: "memory");
}
// FULL completion wait (gmem write landed) — the proven-correct gating
// (.read variant caused the R5/R6 corruption).
__device__ __forceinline__ void bulk_wait_all() {
    asm volatile("cp.async.bulk.wait_group 0;" ::: "memory");
}

// ---------------------------------------------------------------------------
// Kernel 1: both MLPs (R9-proven fast version). 128 blocks x 256 threads;
// 16 rows per block; quad-contiguous transposed x/hidden -> one broadcast
// LDS.128 feeds 4 FMA. PDL trigger at ENTRY: safe because the secondary's
// griddepcontrol.wait blocks until this whole grid completed AND flushed
// (PTX semantics; R4 measured bit-clean) — the trigger only allows the
// secondary's CTAs to launch early and run their W-prefetch prologues.
// ---------------------------------------------------------------------------
__global__ __launch_bounds__(256) void mlp_kernel(
    const float* __restrict__ x,
    const float* __restrict__ nw1, const float* __restrict__ nb1,
    const float* __restrict__ nw2, const float* __restrict__ nb2,
    const float* __restrict__ sw1, const float* __restrict__ sb1,
    const float* __restrict__ sw2, const float* __restrict__ sb2)
{
    cudaTriggerProgrammaticLaunchCompletion();

    __shared__ float s_w1[2][FF * FF];
    __shared__ float s_w2[2][FF * FF];
    __shared__ float s_b1[2][FF], s_b2[2][FF];
    __shared__ __align__(16) float sxT[FF * 16];   // [k][row], quad-contiguous
    __shared__ __align__(16) float shT[FF * 16];   // hidden transposed

    int tid = threadIdx.x;
    int e = tid & 63;
    int g = tid >> 6;        // row quad 0..3

    for (int i = tid; i < FF * FF / 4; i += 256) {
        ((float4*)s_w1[0])[i] = ((const float4*)nw1)[i];
        ((float4*)s_w2[0])[i] = ((const float4*)nw2)[i];
        ((float4*)s_w1[1])[i] = ((const float4*)sw1)[i];
        ((float4*)s_w2[1])[i] = ((const float4*)sw2)[i];
    }
    if (tid < FF) {
        s_b1[0][tid] = nb1[tid];
        s_b2[0][tid] = nb2[tid];
        s_b1[1][tid] = sb1[tid];
        s_b2[1][tid] = sb2[tid];
    }

    int base = blockIdx.x * 16;     // 16 rows per block
    {
        float4 v = ((const float4*)(x + (size_t)base * FF))[tid];
        int r  = (tid * 4) / FF;    // row 0..15
        int k0 = (tid * 4) % FF;
        sxT[(k0 + 0) * 16 + r] = v.x;
        sxT[(k0 + 1) * 16 + r] = v.y;
        sxT[(k0 + 2) * 16 + r] = v.z;
        sxT[(k0 + 3) * 16 + r] = v.w;
    }
    __syncthreads();

    const float4* sxQ = (const float4*)sxT;   // [k*4 + g] = rows 4g..4g+3 at k
    float4*       shQ = (float4*)shT;

    for (int p = 0; p < 2; p++) {   // p=0: n-MLP -> g_x1 ; p=1: s-MLP -> g_s
        float bias = s_b1[p][e];
        float a0 = bias, a1 = bias, a2 = bias, a3 = bias;
        #pragma unroll
        for (int k = 0; k < FF; k++) {
            float  w  = s_w1[p][k * FF + e];
            float4 xv = sxQ[k * 4 + g];       // LDS.128 broadcast
            a0 = fmaf(w, xv.x, a0);
            a1 = fmaf(w, xv.y, a1);
            a2 = fmaf(w, xv.z, a2);
            a3 = fmaf(w, xv.w, a3);
        }
        __syncthreads();   // (p=1) prior shQ consumers done before overwrite
        shQ[e * 4 + g] = make_float4(fmaxf(a0, 0.f), fmaxf(a1, 0.f),
                                     fmaxf(a2, 0.f), fmaxf(a3, 0.f));
        __syncthreads();

        float bias2 = s_b2[p][e];
        float c0 = bias2, c1 = bias2, c2 = bias2, c3 = bias2;
        #pragma unroll
        for (int k = 0; k < FF; k++) {
            float  w  = s_w2[p][k * FF + e];
            float4 hv = shQ[k * 4 + g];       // LDS.128 broadcast
            c0 = fmaf(w, hv.x, c0);
            c1 = fmaf(w, hv.y, c1);
            c2 = fmaf(w, hv.z, c2);
            c3 = fmaf(w, hv.w, c3);
        }
        float* out = p ? g_s : g_x1;
        out[(size_t)(base + 4 * g + 0) * FF + e] = fmaxf(c0, 0.f);
        out[(size_t)(base + 4 * g + 1) * FF + e] = fmaxf(c1, 0.f);
        out[(size_t)(base + 4 * g + 2) * FF + e] = fmaxf(c2, 0.f);
        out[(size_t)(base + 4 * g + 3) * FF + e] = fmaxf(c3, 0.f);
    }
}

// ---------------------------------------------------------------------------
// Kernel 2: fused L1-normalize + einsum + W copy + add s-MLP (R7, proven:
// 41.5us busy, DRAM 68.5%, bit-clean). One block per (b,i). 3-stage 8KB TMA
// ring, prefetch depth 2, stage overwrite gated by FULL wait_group 0.
// PDL: the A-row + tile-0/1 prologue runs BEFORE griddepcontrol.wait, so it
// overlaps mlp execution; g_x1/g_s are only touched after the wait.
// ---------------------------------------------------------------------------
__global__ __launch_bounds__(256, 8) void agg_kernel(
    const float* __restrict__ A,
    const char* __restrict__ W,
    char* __restrict__ outW,
    float* __restrict__ outX2)
{
    __shared__ float sAn[NN];
    __shared__ float4 red2[8][16];  // [warp][e4] partial sums
    __shared__ float warp_s[8];
    __shared__ float sden;
    __shared__ __align__(128) char tile[NSTAGES][TILE_BYTES];
    __shared__ __align__(8) unsigned long long mbar_st[NSTAGES];

    int bi = blockIdx.x;          // b*256 + i
    int b  = bi >> 8;
    int tid = threadIdx.x;

    uint32_t mb[NSTAGES] = { s2u(&mbar_st[0]), s2u(&mbar_st[1]), s2u(&mbar_st[2]) };
    uint32_t tu[NSTAGES] = { s2u(&tile[0][0]), s2u(&tile[1][0]), s2u(&tile[2][0]) };

    if (tid < NSTAGES) mbar_init(mb[tid], 1);

    // L1 denom over the A row (each thread owns one j).
    float a = A[(size_t)bi * NN + tid];
    float v = fabsf(a);
    #pragma unroll
    for (int off = 16; off; off >>= 1) v += __shfl_xor_sync(0xffffffffu, v, off);
    if ((tid & 31) == 0) warp_s[tid >> 5] = v;
    __syncthreads();     // mbar init visible; warp_s ready

    const char* Wrow = W    + (size_t)bi * (NN * FF * 4);
    char*       Orow = outW + (size_t)bi * (NN * FF * 4);

    if (tid == 0) {
        float t = 0.f;
        #pragma unroll
        for (int w = 0; w < 8; w++) t += warp_s[w];
        sden = fmaxf(t, 1e-12f);
        // Prologue: kick off tiles 0 and 1 (overlaps mlp under PDL).
        mbar_expect_tx(mb[0], TILE_BYTES);
        bulk_g2s(tu[0], Wrow, TILE_BYTES, mb[0]);
        mbar_expect_tx(mb[1], TILE_BYTES);
        bulk_g2s(tu[1], Wrow + TILE_BYTES, TILE_BYTES, mb[1]);
    }
    __syncthreads();
    sAn[tid] = a / sden;
    __syncthreads();

    // PDL: blocks until the mlp grid has fully completed and flushed.
    cudaGridDependencySynchronize();

    const float4* x1b = ((const float4*)g_x1) + (size_t)b * (NN * 16);
    int e4 = tid & 15;    // float4 lane (features e4*4 .. e4*4+3)
    int jg = tid >> 4;    // j group 0..15 within tile

    float4 acc = make_float4(0.f, 0.f, 0.f, 0.f);

    #pragma unroll
    for (int t = 0; t < NTILES; t++) {
        int s  = t % NSTAGES;
        int ph = (t / NSTAGES) & 1;
        mbar_wait(mb[s], ph);   // tile t resident in stage s

        if (tid == 0) {
            if (t + 2 < NTILES) {
                // Dest stage (t+2)%3 held tile t-1: consumers finished at the
                // end-of-iter barrier of t-1, and its copy-out store (issued
                // in iter t-1) must be fully complete before overwrite.
                bulk_wait_all();
                int sd = (t + 2) % NSTAGES;
                mbar_expect_tx(mb[sd], TILE_BYTES);
                bulk_g2s(tu[sd], Wrow + (size_t)(t + 2) * TILE_BYTES,
                         TILE_BYTES, mb[sd]);
            }
            // Copy-out of tile t (async-proxy read of stage s).
            bulk_s2g(Orow + (size_t)t * TILE_BYTES, tu[s], TILE_BYTES);
            bulk_commit();
        }

        const float4* Wt = (const float4*)tile[s];
        #pragma unroll
        for (int k = 0; k < TILE_J / 16; k++) {
            int jl = jg + 16 * k;          // j within tile
            int j  = t * TILE_J + jl;
            float4 w   = Wt[jl * 16 + e4];
            float4 x1v = x1b[j * 16 + e4];
            float  tt  = sAn[j];
            acc.x = fmaf(tt * w.x, x1v.x, acc.x);
            acc.y = fmaf(tt * w.y, x1v.y, acc.y);
            acc.z = fmaf(tt * w.z, x1v.z, acc.z);
            acc.w = fmaf(tt * w.w, x1v.w, acc.w);
        }
        __syncthreads();   // all consumers done with stage s before reload
    }

    // Reduce over jg: lanes l and l+16 share the same e4 -> one shfl each.
    acc.x += __shfl_xor_sync(0xffffffffu, acc.x, 16);
    acc.y += __shfl_xor_sync(0xffffffffu, acc.y, 16);
    acc.z += __shfl_xor_sync(0xffffffffu, acc.z, 16);
    acc.w += __shfl_xor_sync(0xffffffffu, acc.w, 16);
    if ((tid & 31) < 16) red2[tid >> 5][e4] = acc;
    __syncthreads();

    if (tid < 16) {
        float4 r = red2[0][tid];
        #pragma unroll
        for (int w = 1; w < 8; w++) {
            float4 t = red2[w][tid];
            r.x += t.x; r.y += t.y; r.z += t.z; r.w += t.w;
        }
        float4 sv = ((const float4*)g_s)[bi * 16 + tid];
        r.x += sv.x; r.y += sv.y; r.z += sv.z; r.w += sv.w;
        ((float4*)outX2)[bi * 16 + tid] = r;
    }

    if (tid == 0) bulk_wait_all();   // full drain of W-tile stores before exit
}

// ---------------------------------------------------------------------------
extern "C" void kernel_launch(void* const* d_in, const int* in_sizes, int n_in,
                              void* d_out, int out_size)
{
    const float* A   = (const float*)d_in[0];
    const float* W   = (const float*)d_in[1];
    const float* x   = (const float*)d_in[2];
    const float* nw1 = (const float*)d_in[3];
    const float* nb1 = (const float*)d_in[4];
    const float* nw2 = (const float*)d_in[5];
    const float* nb2 = (const float*)d_in[6];
    const float* sw1 = (const float*)d_in[7];
    const float* sb1 = (const float*)d_in[8];
    const float* sw2 = (const float*)d_in[9];
    const float* sb2 = (const float*)d_in[10];

    float* outW  = (float*)d_out;            // W passthrough, 33,554,432 floats
    float* outX2 = (float*)d_out + W_ELEMS;  // x2, 131,072 floats

    // Primary: mlp (PDL trigger at entry).
    mlp_kernel<<<128, 256>>>(x, nw1, nb1, nw2, nb2, sw1, sb1, sw2, sb2);

    // Secondary: agg with programmatic stream serialization — its A-row +
    // W-prefetch prologue overlaps mlp; g_x1/g_s gated by the dependency sync.
    cudaLaunchConfig_t cfg = {};
    cfg.gridDim = dim3(ROWS);
    cfg.blockDim = dim3(256);
    cfg.dynamicSmemBytes = 0;
    cfg.stream = 0;
    cudaLaunchAttribute attrs[1];
    attrs[0].id = cudaLaunchAttributeProgrammaticStreamSerialization;
    attrs[0].val.programmaticStreamSerializationAllowed = 1;
    cfg.attrs = attrs;
    cfg.numAttrs = 1;
    cudaLaunchKernelEx(&cfg, agg_kernel, A, (const char*)W, (char*)outW, outX2);
}

// round 14
// speedup vs baseline: 1.1962x; 1.0064x over previous
#include <cuda_runtime.h>
#include <cstdint>

#define BB 8
#define NN 256
#define FF 64
#define ROWS (BB * NN)          // 2048
#define W_ELEMS ((size_t)BB * NN * NN * FF)  // 33,554,432

#define TILE_J 32
#define TILE_BYTES (TILE_J * FF * 4)   // 8192
#define NTILES (NN / TILE_J)           // 8
#define NSTAGES 3
#define MLP_NB 256                     // blocks that run the MLP (8 x-rows each)

// Scratch (allocation-free rule: __device__ globals).
__device__ __align__(16) float g_x1[ROWS * FF];  // relu MLP(n) of x
__device__ __align__(16) float g_s[ROWS * FF];   // relu MLP(s) of x
__device__ int g_cnt[BB];       // per-batch mlp completion counters (target 32)
__device__ unsigned g_fin = 0;  // finish counter for replay-deterministic reset

// ---------------------------------------------------------------------------
// PTX helpers
// ---------------------------------------------------------------------------
__device__ __forceinline__ uint32_t s2u(const void* p) {
    return (uint32_t)__cvta_generic_to_shared(p);
}
__device__ __forceinline__ void mbar_init(uint32_t mbar, uint32_t count) {
    asm volatile("mbarrier.init.shared.b64 [%0], %1;" :: "r"(mbar), "r"(count) : "memory");
}
__device__ __forceinline__ void mbar_expect_tx(uint32_t mbar, uint32_t bytes) {
    asm volatile("mbarrier.arrive.expect_tx.shared.b64 _, [%0], %1;"
                 :: "r"(mbar), "r"(bytes) : "memory");
}
__device__ __forceinline__ void mbar_wait(uint32_t mbar, uint32_t parity) {
    uint32_t done;
    asm volatile(
        "{\n\t.reg .pred p;\n\t"
        "mbarrier.try_wait.parity.acquire.cta.shared::cta.b64 p, [%1], %2;\n\t"
        "selp.b32 %0, 1, 0, p;\n\t}"
        : "=r"(done) : "r"(mbar), "r"(parity) : "memory");
    while (!done) {
        asm volatile(
            "{\n\t.reg .pred p;\n\t"
            "mbarrier.try_wait.parity.acquire.cta.shared::cta.b64 p, [%1], %2, 0x989680;\n\t"
            "selp.b32 %0, 1, 0, p;\n\t}"
            : "=r"(done) : "r"(mbar), "r"(parity) : "memory");
    }
}
__device__ __forceinline__ void bulk_g2s(uint32_t dst_smem, const void* src,
                                         uint32_t bytes, uint32_t mbar) {
    asm volatile(
        "cp.async.bulk.shared::cluster.global.mbarrier::complete_tx::bytes "
        "[%0], [%1], %2, [%3];"
        :: "r"(dst_smem), "l"(src), "r"(bytes), "r"(mbar) : "memory");
}
__device__ __forceinline__ void bulk_s2g(void* dst, uint32_t src_smem, uint32_t bytes) {
    asm volatile("cp.async.bulk.global.shared::cta.bulk_group [%0], [%1], %2;"
                 :: "l"(dst), "r"(src_smem), "r"(bytes) : "memory");
}
__device__ __forceinline__ void bulk_commit() {
    asm volatile("cp.async.bulk.commit_group;" ::: "memory");
}
// FULL completion wait — the proven-correct gating (.read caused corruption).
__device__ __forceinline__ void bulk_wait_all() {
    asm volatile("cp.async.bulk.wait_group 0;" ::: "memory");
}
__device__ __forceinline__ void fence_proxy_async_cta() {
    asm volatile("fence.proxy.async.shared::cta;" ::: "memory");
}

// ---------------------------------------------------------------------------
// ONE fused kernel. Grid = 2048 blocks (one (b,i) row each; 28KB smem ->
// 8 blocks/SM, identical steady-state geometry to the proven R7 agg).
//   Blocks 0..255: run both MLPs for x-rows [8*bi, 8*bi+8) first. Weight
//   matrices are 16KB each and are staged ONE AT A TIME spanning
//   tile[0..1] (16KB) — the R11-proven pattern; x/hidden pair scratch
//   lives in tile[2] (2KB+2KB, disjoint). Then bump the per-batch counter
//   (32 producers per batch) and join the streaming path.
//   Blocks 256..2047: issue A-row loads + 2 W-tile TMA prefetches
//   immediately (their DRAM traffic covers the MLP phase), then tid0 spins
//   on the batch counter.
// Main loop = R7-proven 3-stage 8KB ring: prefetch depth 2, TMA bulk
// stores, full wait_group 0 before stage overwrite.
// ---------------------------------------------------------------------------
__global__ __launch_bounds__(256, 8) void fused_kernel(
    const float* __restrict__ A,
    const char* __restrict__ W,
    const float* __restrict__ x,
    const float* __restrict__ nw1, const float* __restrict__ nb1,
    const float* __restrict__ nw2, const float* __restrict__ nb2,
    const float* __restrict__ sw1, const float* __restrict__ sb1,
    const float* __restrict__ sw2, const float* __restrict__ sb2,
    char* __restrict__ outW,
    float* __restrict__ outX2)
{
    __shared__ __align__(128) char tile[NSTAGES][TILE_BYTES];   // 24KB
    __shared__ __align__(8) unsigned long long mbar_st[NSTAGES];
    __shared__ float sAn[NN];
    __shared__ float4 red2[8][16];
    __shared__ float warp_s[8];
    __shared__ float sden;

    int bi  = blockIdx.x;          // b*256 + i
    int b   = bi >> 8;
    int tid = threadIdx.x;

    uint32_t mb[NSTAGES] = { s2u(&mbar_st[0]), s2u(&mbar_st[1]), s2u(&mbar_st[2]) };
    uint32_t tu[NSTAGES] = { s2u(&tile[0][0]), s2u(&tile[1][0]), s2u(&tile[2][0]) };
    if (tid < NSTAGES) mbar_init(mb[tid], 1);

    // L1 denom over the A row (each thread owns one j).
    float a = A[(size_t)bi * NN + tid];
    float v = fabsf(a);
    #pragma unroll
    for (int off = 16; off; off >>= 1) v += __shfl_xor_sync(0xffffffffu, v, off);
    if ((tid & 31) == 0) warp_s[tid >> 5] = v;
    __syncthreads();     // warp_s ready; mbar init visible

    bool is_mlp = (bi < MLP_NB);

    if (is_mlp) {
        // ---- MLP phase for x-rows [8*bi, 8*bi+8) ----
        int R0 = bi * 8;
        int e = tid & 63;
        int g = tid >> 6;                         // row-pair 0..3
        float2* sxP = (float2*)tile[2];           // [64][4] x pairs (2KB)
        float2* shP = (float2*)(tile[2] + 4096);  // [64][4] hidden pairs (2KB)
        const float* sWm = (const float*)tile[0]; // staged 16KB weight matrix
        float4* stage = (float4*)tile[0];         // 16KB staging span tile[0..1]

        if (tid < 128) {   // load 8x64 x block, transposed into pair layout
            float4 xv = ((const float4*)(x + (size_t)R0 * FF))[tid];
            int row = tid >> 4;          // local row 0..7
            int k0  = (tid & 15) * 4;
            ((float*)&sxP[(k0 + 0) * 4 + (row >> 1)])[row & 1] = xv.x;
            ((float*)&sxP[(k0 + 1) * 4 + (row >> 1)])[row & 1] = xv.y;
            ((float*)&sxP[(k0 + 2) * 4 + (row >> 1)])[row & 1] = xv.z;
            ((float*)&sxP[(k0 + 3) * 4 + (row >> 1)])[row & 1] = xv.w;
        }

        for (int p = 0; p < 2; p++) {   // p=0: n-MLP -> g_x1 ; p=1: s-MLP -> g_s
            const float* w1 = p ? sw1 : nw1;
            const float* w2 = p ? sw2 : nw2;
            const float* b1 = p ? sb1 : nb1;
            const float* b2 = p ? sb2 : nb2;

            // Stage w1 (16KB) across tile[0..1].
            #pragma unroll
            for (int jj = 0; jj < 4; jj++)
                stage[tid + jj * 256] = ((const float4*)w1)[tid + jj * 256];
            __syncthreads();   // staging + x-transpose (p=0) + prior-p reads done

            float bias = __ldg(&b1[e]);
            float h0 = bias, h1 = bias;
            #pragma unroll
            for (int k = 0; k < FF; k++) {
                float  w  = sWm[k * FF + e];
                float2 xv = sxP[k * 4 + g];
                h0 = fmaf(w, xv.x, h0);
                h1 = fmaf(w, xv.y, h1);
            }
            __syncthreads();   // w1 reads done before restage; prior shP consumed

            shP[e * 4 + g] = make_float2(fmaxf(h0, 0.f), fmaxf(h1, 0.f));
            // Stage w2 (16KB) across tile[0..1] (disjoint from shP in tile[2]).
            #pragma unroll
            for (int jj = 0; jj < 4; jj++)
                stage[tid + jj * 256] = ((const float4*)w2)[tid + jj * 256];
            __syncthreads();   // w2 staged + shP written

            float bias2 = __ldg(&b2[e]);
            float c0 = bias2, c1 = bias2;
            #pragma unroll
            for (int k = 0; k < FF; k++) {
                float  w  = sWm[k * FF + e];
                float2 hv = shP[k * 4 + g];
                c0 = fmaf(w, hv.x, c0);
                c1 = fmaf(w, hv.y, c1);
            }
            float* out = p ? g_s : g_x1;
            out[(size_t)(R0 + 2 * g + 0) * FF + e] = fmaxf(c0, 0.f);
            out[(size_t)(R0 + 2 * g + 1) * FF + e] = fmaxf(c1, 0.f);
            __syncthreads();   // w2/shP reads done before next restage / TMA
        }

        __threadfence();       // make g_x1/g_s globally visible (release)
        __syncthreads();       // all threads' fences precede the signal
        if (tid == 0) atomicAdd(&g_cnt[bi >> 5], 1);   // batch of rows 8bi..
    }

    const char* Wrow = W    + (size_t)bi * (NN * FF * 4);
    char*       Orow = outW + (size_t)bi * (NN * FF * 4);

    if (tid == 0) {
        float t = 0.f;
        #pragma unroll
        for (int w = 0; w < 8; w++) t += warp_s[w];
        sden = fmaxf(t, 1e-12f);
        if (is_mlp) fence_proxy_async_cta();   // generic tile writes -> async proxy
        // Prologue: kick off tiles 0 and 1 (non-mlp blocks issue these
        // immediately — their traffic covers the MLP phase).
        mbar_expect_tx(mb[0], TILE_BYTES);
        bulk_g2s(tu[0], Wrow, TILE_BYTES, mb[0]);
        mbar_expect_tx(mb[1], TILE_BYTES);
        bulk_g2s(tu[1], Wrow + TILE_BYTES, TILE_BYTES, mb[1]);
    }
    __syncthreads();
    sAn[tid] = a / sden;

    // ---- wait for this batch's MLP outputs (per-batch release) ----
    if (tid == 0) {
        while (*((volatile int*)&g_cnt[b]) < 32) __nanosleep(128);
        __threadfence();       // acquire pairing with the producers' release
    }
    __syncthreads();           // sAn ready + mlp outputs visible to all threads

    const float4* x1b = ((const float4*)g_x1) + (size_t)b * (NN * 16);
    int e4 = tid & 15;    // float4 lane (features e4*4 .. e4*4+3)
    int jg = tid >> 4;    // j group 0..15 within tile

    float4 acc = make_float4(0.f, 0.f, 0.f, 0.f);

    #pragma unroll
    for (int t = 0; t < NTILES; t++) {
        int s  = t % NSTAGES;
        int ph = (t / NSTAGES) & 1;
        mbar_wait(mb[s], ph);   // tile t resident in stage s

        if (tid == 0) {
            if (t + 2 < NTILES) {
                // Dest stage (t+2)%3 held tile t-1: consumers finished at the
                // end-of-iter barrier of t-1, and its copy-out store (issued
                // in iter t-1) must be fully complete before overwrite.
                bulk_wait_all();
                int sd = (t + 2) % NSTAGES;
                mbar_expect_tx(mb[sd], TILE_BYTES);
                bulk_g2s(tu[sd], Wrow + (size_t)(t + 2) * TILE_BYTES,
                         TILE_BYTES, mb[sd]);
            }
            // Copy-out of tile t (async-proxy read of stage s).
            bulk_s2g(Orow + (size_t)t * TILE_BYTES, tu[s], TILE_BYTES);
            bulk_commit();
        }

        const float4* Wt = (const float4*)tile[s];
        #pragma unroll
        for (int k = 0; k < TILE_J / 16; k++) {
            int jl = jg + 16 * k;          // j within tile
            int j  = t * TILE_J + jl;
            float4 w   = Wt[jl * 16 + e4];
            float4 x1v = x1b[j * 16 + e4];
            float  tt  = sAn[j];
            acc.x = fmaf(tt * w.x, x1v.x, acc.x);
            acc.y = fmaf(tt * w.y, x1v.y, acc.y);
            acc.z = fmaf(tt * w.z, x1v.z, acc.z);
            acc.w = fmaf(tt * w.w, x1v.w, acc.w);
        }
        __syncthreads();   // all consumers done with stage s before reload
    }

    // Reduce over jg: lanes l and l+16 share the same e4 -> one shfl each.
    acc.x += __shfl_xor_sync(0xffffffffu, acc.x, 16);
    acc.y += __shfl_xor_sync(0xffffffffu, acc.y, 16);
    acc.z += __shfl_xor_sync(0xffffffffu, acc.z, 16);
    acc.w += __shfl_xor_sync(0xffffffffu, acc.w, 16);
    if ((tid & 31) < 16) red2[tid >> 5][e4] = acc;
    __syncthreads();

    if (tid < 16) {
        float4 r = red2[0][tid];
        #pragma unroll
        for (int w = 1; w < 8; w++) {
            float4 t = red2[w][tid];
            r.x += t.x; r.y += t.y; r.z += t.z; r.w += t.w;
        }
        float4 sv = ((const float4*)g_s)[bi * 16 + tid];
        r.x += sv.x; r.y += sv.y; r.z += sv.z; r.w += sv.w;
        ((float4*)outX2)[bi * 16 + tid] = r;
    }

    if (tid == 0) {
        bulk_wait_all();   // drain W-tile stores
        // Replay-determinism: last finishing block resets sync state. Every
        // block reaches here only AFTER passing its counter wait, so the
        // reset can never race an in-progress wait.
        unsigned f = atomicAdd(&g_fin, 1u);
        if (f == (unsigned)(ROWS - 1)) {
            #pragma unroll
            for (int i = 0; i < BB; i++) g_cnt[i] = 0;
            g_fin = 0u;
            __threadfence();
        }
    }
}

// ---------------------------------------------------------------------------
extern "C" void kernel_launch(void* const* d_in, const int* in_sizes, int n_in,
                              void* d_out, int out_size)
{
    const float* A   = (const float*)d_in[0];
    const float* W   = (const float*)d_in[1];
    const float* x   = (const float*)d_in[2];
    const float* nw1 = (const float*)d_in[3];
    const float* nb1 = (const float*)d_in[4];
    const float* nw2 = (const float*)d_in[5];
    const float* nb2 = (const float*)d_in[6];
    const float* sw1 = (const float*)d_in[7];
    const float* sb1 = (const float*)d_in[8];
    const float* sw2 = (const float*)d_in[9];
    const float* sb2 = (const float*)d_in[10];

    float* outW  = (float*)d_out;            // W passthrough, 33,554,432 floats
    float* outX2 = (float*)d_out + W_ELEMS;  // x2, 131,072 floats

    fused_kernel<<<ROWS, 256>>>(A, (const char*)W, x,
                                nw1, nb1, nw2, nb2,
                                sw1, sb1, sw2, sb2,
                                (char*)outW, outX2);
}

// round 15
// speedup vs baseline: 1.2268x; 1.0256x over previous
#include <cuda_runtime.h>
#include <cstdint>

#define BB 8
#define NN 256
#define FF 64
#define ROWS (BB * NN)          // 2048
#define W_ELEMS ((size_t)BB * NN * NN * FF)  // 33,554,432

#define TILE_J 32
#define TILE_BYTES (TILE_J * FF * 4)   // 8192
#define NTILES (NN / TILE_J)           // 8
#define NSTAGES 3
#define MLP_NB 512                     // 256 n-MLP blocks + 256 s-MLP blocks

// Scratch (allocation-free rule: __device__ globals).
__device__ __align__(16) float g_x1[ROWS * FF];  // relu MLP(n) of x
__device__ __align__(16) float g_s[ROWS * FF];   // relu MLP(s) of x
__device__ int g_cnt[BB];       // per-batch mlp completion counters (target 64)
__device__ unsigned g_fin = 0;  // finish counter for replay-deterministic reset

// ---------------------------------------------------------------------------
// PTX helpers
// ---------------------------------------------------------------------------
__device__ __forceinline__ uint32_t s2u(const void* p) {
    return (uint32_t)__cvta_generic_to_shared(p);
}
__device__ __forceinline__ void mbar_init(uint32_t mbar, uint32_t count) {
    asm volatile("mbarrier.init.shared.b64 [%0], %1;" :: "r"(mbar), "r"(count) : "memory");
}
__device__ __forceinline__ void mbar_expect_tx(uint32_t mbar, uint32_t bytes) {
    asm volatile("mbarrier.arrive.expect_tx.shared.b64 _, [%0], %1;"
                 :: "r"(mbar), "r"(bytes) : "memory");
}
__device__ __forceinline__ void mbar_wait(uint32_t mbar, uint32_t parity) {
    uint32_t done;
    asm volatile(
        "{\n\t.reg .pred p;\n\t"
        "mbarrier.try_wait.parity.acquire.cta.shared::cta.b64 p, [%1], %2;\n\t"
        "selp.b32 %0, 1, 0, p;\n\t}"
        : "=r"(done) : "r"(mbar), "r"(parity) : "memory");
    while (!done) {
        asm volatile(
            "{\n\t.reg .pred p;\n\t"
            "mbarrier.try_wait.parity.acquire.cta.shared::cta.b64 p, [%1], %2, 0x989680;\n\t"
            "selp.b32 %0, 1, 0, p;\n\t}"
            : "=r"(done) : "r"(mbar), "r"(parity) : "memory");
    }
}
__device__ __forceinline__ void bulk_g2s(uint32_t dst_smem, const void* src,
                                         uint32_t bytes, uint32_t mbar) {
    asm volatile(
        "cp.async.bulk.shared::cluster.global.mbarrier::complete_tx::bytes "
        "[%0], [%1], %2, [%3];"
        :: "r"(dst_smem), "l"(src), "r"(bytes), "r"(mbar) : "memory");
}
__device__ __forceinline__ void bulk_s2g(void* dst, uint32_t src_smem, uint32_t bytes) {
    asm volatile("cp.async.bulk.global.shared::cta.bulk_group [%0], [%1], %2;"
                 :: "l"(dst), "r"(src_smem), "r"(bytes) : "memory");
}
__device__ __forceinline__ void bulk_commit() {
    asm volatile("cp.async.bulk.commit_group;" ::: "memory");
}
// FULL completion wait — the proven-correct gating (.read caused corruption).
__device__ __forceinline__ void bulk_wait_all() {
    asm volatile("cp.async.bulk.wait_group 0;" ::: "memory");
}
__device__ __forceinline__ void fence_proxy_async_cta() {
    asm volatile("fence.proxy.async.shared::cta;" ::: "memory");
}

// ---------------------------------------------------------------------------
// ONE fused kernel. Grid = 2048 blocks (one (b,i) row each; 28KB smem ->
// 8 blocks/SM, R7-identical steady-state geometry).
//   Blocks 0..255:   n-MLP only (-> g_x1) for x-rows [8*bi, 8*bi+8).
//   Blocks 256..511: s-MLP only (-> g_s)  for x-rows [8*(bi-256), ...+8).
//   Splitting the two MLPs across disjoint groups HALVES each block's
//   serial chain (2 weight stagings + 2 FMA loops instead of 4+4), which
//   sets the startup bubble. Weight staged ONE matrix at a time across
//   tile[0..1] (16KB, R14-proven); x/hidden pairs in tile[2] (disjoint).
//   Per-batch counter target = 64 (32 n + 32 s producers).
//   Blocks 512..2047: issue A-row + 2 W-tile TMA prefetches immediately
//   (their DRAM traffic covers the MLP phase), then tid0 spins.
// Main loop = R7-proven 3-stage 8KB ring: prefetch depth 2, TMA bulk
// stores, full wait_group 0 before stage overwrite.
// ---------------------------------------------------------------------------
__global__ __launch_bounds__(256, 8) void fused_kernel(
    const float* __restrict__ A,
    const char* __restrict__ W,
    const float* __restrict__ x,
    const float* __restrict__ nw1, const float* __restrict__ nb1,
    const float* __restrict__ nw2, const float* __restrict__ nb2,
    const float* __restrict__ sw1, const float* __restrict__ sb1,
    const float* __restrict__ sw2, const float* __restrict__ sb2,
    char* __restrict__ outW,
    float* __restrict__ outX2)
{
    __shared__ __align__(128) char tile[NSTAGES][TILE_BYTES];   // 24KB
    __shared__ __align__(8) unsigned long long mbar_st[NSTAGES];
    __shared__ float sAn[NN];
    __shared__ float4 red2[8][16];
    __shared__ float warp_s[8];
    __shared__ float sden;

    int bi  = blockIdx.x;          // b*256 + i
    int b   = bi >> 8;
    int tid = threadIdx.x;

    uint32_t mb[NSTAGES] = { s2u(&mbar_st[0]), s2u(&mbar_st[1]), s2u(&mbar_st[2]) };
    uint32_t tu[NSTAGES] = { s2u(&tile[0][0]), s2u(&tile[1][0]), s2u(&tile[2][0]) };
    if (tid < NSTAGES) mbar_init(mb[tid], 1);

    // L1 denom over the A row (each thread owns one j).
    float a = A[(size_t)bi * NN + tid];
    float v = fabsf(a);
    #pragma unroll
    for (int off = 16; off; off >>= 1) v += __shfl_xor_sync(0xffffffffu, v, off);
    if ((tid & 31) == 0) warp_s[tid >> 5] = v;
    __syncthreads();     // warp_s ready; mbar init visible

    bool is_mlp = (bi < MLP_NB);

    if (is_mlp) {
        // ---- one MLP network for 8 x-rows; which net by block group ----
        int which = bi >> 8;               // 0 = n-MLP, 1 = s-MLP
        int R0 = (bi & 255) * 8;           // first x-row
        const float* w1 = which ? sw1 : nw1;
        const float* w2 = which ? sw2 : nw2;
        const float* b1 = which ? sb1 : nb1;
        const float* b2 = which ? sb2 : nb2;
        float* out = which ? g_s : g_x1;

        int e = tid & 63;
        int g = tid >> 6;                         // row-pair 0..3
        float2* sxP = (float2*)tile[2];           // [64][4] x pairs (2KB)
        float2* shP = (float2*)(tile[2] + 4096);  // [64][4] hidden pairs (2KB)
        const float* sWm = (const float*)tile[0]; // staged 16KB weight matrix
        float4* stage = (float4*)tile[0];         // 16KB span tile[0..1]

        if (tid < 128) {   // load 8x64 x block, transposed into pair layout
            float4 xv = ((const float4*)(x + (size_t)R0 * FF))[tid];
            int row = tid >> 4;          // local row 0..7
            int k0  = (tid & 15) * 4;
            ((float*)&sxP[(k0 + 0) * 4 + (row >> 1)])[row & 1] = xv.x;
            ((float*)&sxP[(k0 + 1) * 4 + (row >> 1)])[row & 1] = xv.y;
            ((float*)&sxP[(k0 + 2) * 4 + (row >> 1)])[row & 1] = xv.z;
            ((float*)&sxP[(k0 + 3) * 4 + (row >> 1)])[row & 1] = xv.w;
        }

        // Stage w1 (16KB) across tile[0..1].
        #pragma unroll
        for (int jj = 0; jj < 4; jj++)
            stage[tid + jj * 256] = ((const float4*)w1)[tid + jj * 256];
        __syncthreads();   // staging + x-transpose visible

        float bias = __ldg(&b1[e]);
        float h0 = bias, h1 = bias;
        #pragma unroll
        for (int k = 0; k < FF; k++) {
            float  w  = sWm[k * FF + e];
            float2 xv = sxP[k * 4 + g];
            h0 = fmaf(w, xv.x, h0);
            h1 = fmaf(w, xv.y, h1);
        }
        __syncthreads();   // w1 reads done before restage

        shP[e * 4 + g] = make_float2(fmaxf(h0, 0.f), fmaxf(h1, 0.f));
        // Stage w2 (16KB) across tile[0..1] (disjoint from shP in tile[2]).
        #pragma unroll
        for (int jj = 0; jj < 4; jj++)
            stage[tid + jj * 256] = ((const float4*)w2)[tid + jj * 256];
        __syncthreads();   // w2 staged + shP written

        float bias2 = __ldg(&b2[e]);
        float c0 = bias2, c1 = bias2;
        #pragma unroll
        for (int k = 0; k < FF; k++) {
            float  w  = sWm[k * FF + e];
            float2 hv = shP[k * 4 + g];
            c0 = fmaf(w, hv.x, c0);
            c1 = fmaf(w, hv.y, c1);
        }
        out[(size_t)(R0 + 2 * g + 0) * FF + e] = fmaxf(c0, 0.f);
        out[(size_t)(R0 + 2 * g + 1) * FF + e] = fmaxf(c1, 0.f);
        __syncthreads();   // tile readers done before TMA reuses it

        __threadfence();   // make the outputs globally visible (release)
        __syncthreads();   // all threads' fences precede the signal
        if (tid == 0) atomicAdd(&g_cnt[(bi & 255) >> 5], 1);
    }

    const char* Wrow = W    + (size_t)bi * (NN * FF * 4);
    char*       Orow = outW + (size_t)bi * (NN * FF * 4);

    if (tid == 0) {
        float t = 0.f;
        #pragma unroll
        for (int w = 0; w < 8; w++) t += warp_s[w];
        sden = fmaxf(t, 1e-12f);
        if (is_mlp) fence_proxy_async_cta();   // generic tile writes -> async proxy
        // Prologue: kick off tiles 0 and 1 (non-mlp blocks issue these
        // immediately — their traffic covers the MLP phase).
        mbar_expect_tx(mb[0], TILE_BYTES);
        bulk_g2s(tu[0], Wrow, TILE_BYTES, mb[0]);
        mbar_expect_tx(mb[1], TILE_BYTES);
        bulk_g2s(tu[1], Wrow + TILE_BYTES, TILE_BYTES, mb[1]);
    }
    __syncthreads();
    sAn[tid] = a / sden;

    // ---- wait for this batch's MLP outputs (64 producers: 32 n + 32 s) ----
    if (tid == 0) {
        while (*((volatile int*)&g_cnt[b]) < 64) __nanosleep(128);
        __threadfence();       // acquire pairing with the producers' release
    }
    __syncthreads();           // sAn ready + mlp outputs visible to all threads

    const float4* x1b = ((const float4*)g_x1) + (size_t)b * (NN * 16);
    int e4 = tid & 15;    // float4 lane (features e4*4 .. e4*4+3)
    int jg = tid >> 4;    // j group 0..15 within tile

    float4 acc = make_float4(0.f, 0.f, 0.f, 0.f);

    #pragma unroll
    for (int t = 0; t < NTILES; t++) {
        int s  = t % NSTAGES;
        int ph = (t / NSTAGES) & 1;
        mbar_wait(mb[s], ph);   // tile t resident in stage s

        if (tid == 0) {
            if (t + 2 < NTILES) {
                // Dest stage (t+2)%3 held tile t-1: consumers finished at the
                // end-of-iter barrier of t-1, and its copy-out store (issued
                // in iter t-1) must be fully complete before overwrite.
                bulk_wait_all();
                int sd = (t + 2) % NSTAGES;
                mbar_expect_tx(mb[sd], TILE_BYTES);
                bulk_g2s(tu[sd], Wrow + (size_t)(t + 2) * TILE_BYTES,
                         TILE_BYTES, mb[sd]);
            }
            // Copy-out of tile t (async-proxy read of stage s).
            bulk_s2g(Orow + (size_t)t * TILE_BYTES, tu[s], TILE_BYTES);
            bulk_commit();
        }

        const float4* Wt = (const float4*)tile[s];
        #pragma unroll
        for (int k = 0; k < TILE_J / 16; k++) {
            int jl = jg + 16 * k;          // j within tile
            int j  = t * TILE_J + jl;
            float4 w   = Wt[jl * 16 + e4];
            float4 x1v = x1b[j * 16 + e4];
            float  tt  = sAn[j];
            acc.x = fmaf(tt * w.x, x1v.x, acc.x);
            acc.y = fmaf(tt * w.y, x1v.y, acc.y);
            acc.z = fmaf(tt * w.z, x1v.z, acc.z);
            acc.w = fmaf(tt * w.w, x1v.w, acc.w);
        }
        __syncthreads();   // all consumers done with stage s before reload
    }

    // Reduce over jg: lanes l and l+16 share the same e4 -> one shfl each.
    acc.x += __shfl_xor_sync(0xffffffffu, acc.x, 16);
    acc.y += __shfl_xor_sync(0xffffffffu, acc.y, 16);
    acc.z += __shfl_xor_sync(0xffffffffu, acc.z, 16);
    acc.w += __shfl_xor_sync(0xffffffffu, acc.w, 16);
    if ((tid & 31) < 16) red2[tid >> 5][e4] = acc;
    __syncthreads();

    if (tid < 16) {
        float4 r = red2[0][tid];
        #pragma unroll
        for (int w = 1; w < 8; w++) {
            float4 t = red2[w][tid];
            r.x += t.x; r.y += t.y; r.z += t.z; r.w += t.w;
        }
        float4 sv = ((const float4*)g_s)[bi * 16 + tid];
        r.x += sv.x; r.y += sv.y; r.z += sv.z; r.w += sv.w;
        ((float4*)outX2)[bi * 16 + tid] = r;
    }

    if (tid == 0) {
        bulk_wait_all();   // drain W-tile stores
        // Replay-determinism: last finishing block resets sync state. Every
        // block reaches here only AFTER passing its counter wait, so the
        // reset can never race an in-progress wait.
        unsigned f = atomicAdd(&g_fin, 1u);
        if (f == (unsigned)(ROWS - 1)) {
            #pragma unroll
            for (int i = 0; i < BB; i++) g_cnt[i] = 0;
            g_fin = 0u;
            __threadfence();
        }
    }
}

// ---------------------------------------------------------------------------
extern "C" void kernel_launch(void* const* d_in, const int* in_sizes, int n_in,
                              void* d_out, int out_size)
{
    const float* A   = (const float*)d_in[0];
    const float* W   = (const float*)d_in[1];
    const float* x   = (const float*)d_in[2];
    const float* nw1 = (const float*)d_in[3];
    const float* nb1 = (const float*)d_in[4];
    const float* nw2 = (const float*)d_in[5];
    const float* nb2 = (const float*)d_in[6];
    const float* sw1 = (const float*)d_in[7];
    const float* sb1 = (const float*)d_in[8];
    const float* sw2 = (const float*)d_in[9];
    const float* sb2 = (const float*)d_in[10];

    float* outW  = (float*)d_out;            // W passthrough, 33,554,432 floats
    float* outX2 = (float*)d_out + W_ELEMS;  // x2, 131,072 floats

    fused_kernel<<<ROWS, 256>>>(A, (const char*)W, x,
                                nw1, nb1, nw2, nb2,
                                sw1, sb1, sw2, sb2,
                                (char*)outW, outX2);
}